// round 6
// baseline (speedup 1.0000x reference)
#include <cuda_runtime.h>
#include <math.h>

// Problem constants
#define T_TOK 4096
#define H_DIM 1024
#define I_DIM 4096
#define E_EXP 8
#define K_TOP 2
#define P_PAIR (T_TOK * K_TOP)

// ---------------- scratch (static device globals; no runtime alloc) ----------
// Interleaved (hi,lo) tf32 split operands, stored as uint2 per fp32 element.
__device__ uint2 g_x_s[(size_t)T_TOK * H_DIM];              // 33.5 MB
__device__ uint2 g_wg_s[(size_t)E_EXP * H_DIM * I_DIM];     // 268 MB
__device__ uint2 g_wu_s[(size_t)E_EXP * H_DIM * I_DIM];     // 268 MB
__device__ uint2 g_wd_s[(size_t)E_EXP * I_DIM * H_DIM];     // 268 MB
__device__ uint2 g_hdn_s[(size_t)P_PAIR * I_DIM];           // 268 MB (pre-split)
__device__ float g_pairout[(size_t)P_PAIR * H_DIM];         // 33.5 MB
__device__ int   g_perm[P_PAIR];
__device__ float g_pairw[P_PAIR];
__device__ int   g_pos[P_PAIR];
__device__ int   g_tki[T_TOK * K_TOP];
__device__ float g_tkw[T_TOK * K_TOP];
__device__ int   g_counts[E_EXP];
__device__ int   g_offsets[E_EXP];
__device__ int   g_cursor[E_EXP];
__device__ float g_load[E_EXP];

// ---------------- tf32 helpers ------------------------------------------------
__device__ __forceinline__ unsigned cvt_tf32(float x) {
    unsigned u; asm("cvt.rna.tf32.f32 %0, %1;" : "=r"(u) : "f"(x)); return u;
}
__device__ __forceinline__ uint2 split2(float v) {
    unsigned hi = cvt_tf32(v);
    unsigned lo = cvt_tf32(v - __uint_as_float(hi));
    uint2 r; r.x = hi; r.y = lo; return r;
}
__device__ __forceinline__ void mma8(float* c, const unsigned* a, const unsigned* b) {
    asm volatile(
        "mma.sync.aligned.m16n8k8.row.col.f32.tf32.tf32.f32 "
        "{%0,%1,%2,%3}, {%4,%5,%6,%7}, {%8,%9}, {%0,%1,%2,%3};"
        : "+f"(c[0]), "+f"(c[1]), "+f"(c[2]), "+f"(c[3])
        : "r"(a[0]), "r"(a[1]), "r"(a[2]), "r"(a[3]), "r"(b[0]), "r"(b[1]));
}
// 3-term tf32: Ah*Bh + Al*Bh + Ah*Bl, operands pre-split in (hi,lo) uint2.
__device__ __forceinline__ void mma3(float* c, const uint2 a[4], uint2 b0, uint2 b1) {
    unsigned ah[4] = {a[0].x, a[1].x, a[2].x, a[3].x};
    unsigned al[4] = {a[0].y, a[1].y, a[2].y, a[3].y};
    unsigned bh[2] = {b0.x, b1.x};
    unsigned bl[2] = {b0.y, b1.y};
    mma8(c, ah, bh);
    mma8(c, al, bh);
    mma8(c, ah, bl);
}
__device__ __forceinline__ void cp16(unsigned dst, const void* src) {
    asm volatile("cp.async.cg.shared.global [%0], [%1], 16;" :: "r"(dst), "l"(src));
}
#define CP_COMMIT() asm volatile("cp.async.commit_group;")
#define CP_WAIT1()  asm volatile("cp.async.wait_group 1;")
#define CP_WAIT0()  asm volatile("cp.async.wait_group 0;")

// ---------------- small kernels ----------------------------------------------
__global__ void zero_kernel() {
    int i = threadIdx.x;
    if (i < E_EXP) { g_counts[i] = 0; g_load[i] = 0.f; }
}

__global__ void router_kernel(const float* __restrict__ x,
                              const float* __restrict__ gw) {
    int t = blockIdx.x;
    int w = threadIdx.x >> 5, lane = threadIdx.x & 31;
    __shared__ float logits[E_EXP];
    const float* xr = x + (size_t)t * H_DIM;
    float s = 0.f;
    for (int h = lane; h < H_DIM; h += 32)
        s += xr[h] * gw[h * E_EXP + w];
    #pragma unroll
    for (int o = 16; o; o >>= 1) s += __shfl_xor_sync(0xffffffffu, s, o);
    if (lane == 0) logits[w] = s;
    __syncthreads();
    if (threadIdx.x == 0) {
        float mx = logits[0];
        #pragma unroll
        for (int e = 1; e < E_EXP; e++) mx = fmaxf(mx, logits[e]);
        float p[E_EXP], den = 0.f;
        #pragma unroll
        for (int e = 0; e < E_EXP; e++) { p[e] = expf(logits[e] - mx); den += p[e]; }
        #pragma unroll
        for (int e = 0; e < E_EXP; e++) p[e] /= den;
        int i0 = 0;
        #pragma unroll
        for (int e = 1; e < E_EXP; e++) if (p[e] > p[i0]) i0 = e;
        int i1 = -1;
        #pragma unroll
        for (int e = 0; e < E_EXP; e++) {
            if (e == i0) continue;
            if (i1 < 0 || p[e] > p[i1]) i1 = e;
        }
        float w0 = p[i0], w1 = p[i1], sm = w0 + w1;
        g_tki[t * 2 + 0] = i0; g_tki[t * 2 + 1] = i1;
        g_tkw[t * 2 + 0] = w0 / sm; g_tkw[t * 2 + 1] = w1 / sm;
        atomicAdd(&g_counts[i0], 1); atomicAdd(&g_counts[i1], 1);
        atomicAdd(&g_load[i0], w0);  atomicAdd(&g_load[i1], w1);
    }
}

__global__ void finalize_router(float* out_aux, int write_aux) {
    if (threadIdx.x == 0) {
        int off = 0;
        for (int e = 0; e < E_EXP; e++) {
            g_offsets[e] = off; g_cursor[e] = off; off += g_counts[e];
        }
        if (write_aux) {
            float aux = 0.f;
            for (int e = 0; e < E_EXP; e++) {
                float Pe = g_load[e] / (float)T_TOK;
                float Pt = (float)g_counts[e] / (float)(T_TOK * K_TOP);
                aux += Pe * Pt;
            }
            *out_aux = aux * (float)E_EXP * 0.001f;
        }
    }
}

__global__ void scatter_kernel() {
    int t = blockIdx.x * blockDim.x + threadIdx.x;
    if (t >= T_TOK) return;
    #pragma unroll
    for (int k = 0; k < K_TOP; k++) {
        int e = g_tki[t * 2 + k];
        int p = atomicAdd(&g_cursor[e], 1);
        g_perm[p] = t;
        g_pairw[p] = g_tkw[t * 2 + k];
        g_pos[t * 2 + k] = p;
    }
}

// ---------------- preprocessing: fp32 -> interleaved (hi,lo) tf32 ------------
__global__ void split_kernel(const float* __restrict__ src,
                             uint2* __restrict__ dst, long n4) {
    long stride = (long)gridDim.x * blockDim.x;
    for (long i = (long)blockIdx.x * blockDim.x + threadIdx.x; i < n4; i += stride) {
        float4 v = ((const float4*)src)[i];
        uint2 s0 = split2(v.x), s1 = split2(v.y), s2 = split2(v.z), s3 = split2(v.w);
        uint4 o0, o1;
        o0.x = s0.x; o0.y = s0.y; o0.z = s1.x; o0.w = s1.y;
        o1.x = s2.x; o1.y = s2.y; o1.z = s3.x; o1.w = s3.y;
        ((uint4*)dst)[i * 2 + 0] = o0;
        ((uint4*)dst)[i * 2 + 1] = o1;
    }
}

// ---------------- GEMM1: hdn = silu(X@wg[e]) * (X@wu[e]) ---------------------
// Block 128(M) x 128(N), KS=16, 2-stage cp.async. 8 warps: 4(M)x2(N),
// warp tile 32x64 for BOTH G and U (shared A frags). All operands pre-split.
// smem layout (uint2 units): As 2x2560, Bg 2x2176, Bu 2x2176.
#define F1_ASZ 2560     // 128 rows * 20 stride
#define F1_BSZ 2176     // 16 rows * 136 stride
__global__ void __launch_bounds__(256, 1) ffn1_kernel(
    const float* __restrict__ x_unused) {
    extern __shared__ uint2 sm1[];
    uint2* As = sm1;                    // [2][128][20]
    uint2* Bg = sm1 + 2 * F1_ASZ;       // [2][16][136]
    uint2* Bu = Bg + 2 * F1_BSZ;

    const int e = blockIdx.z;
    const int cnt = g_counts[e];
    const int m0 = blockIdx.x * 128;
    if (m0 >= cnt) return;
    const int beg = g_offsets[e];
    const int n0 = blockIdx.y * 128;

    __shared__ int perm_s[128];
    const int tid = threadIdx.x;
    if (tid < 128) {
        int r = m0 + tid;
        perm_s[tid] = g_perm[beg + (r < cnt ? r : cnt - 1)];
    }
    __syncthreads();

    // global source pointers
    const int ar = tid >> 2;            // A rows 0..63 (+64)
    const int ac = (tid & 3) * 4;       // elem offset 0,4,8,12 (covers 4 elems)
    const uint2* axr0 = g_x_s + (size_t)perm_s[ar] * H_DIM + ac;
    const uint2* axr1 = g_x_s + (size_t)perm_s[ar + 64] * H_DIM + ac;
    const int bk = tid >> 4;            // 0..15
    const int bn = (tid & 15) * 8;      // elem 0..120 (covers 8 elems)
    const uint2* bgp = g_wg_s + (size_t)e * H_DIM * I_DIM + (size_t)bk * I_DIM + n0 + bn;
    const uint2* bup = g_wu_s + (size_t)e * H_DIM * I_DIM + (size_t)bk * I_DIM + n0 + bn;

    unsigned sm_u = (unsigned)__cvta_generic_to_shared(sm1);
    const unsigned a_d0 = sm_u + (unsigned)(ar * 20 + ac) * 8;
    const unsigned a_d1 = sm_u + (unsigned)((ar + 64) * 20 + ac) * 8;
    const unsigned bg_d = sm_u + (unsigned)(2 * F1_ASZ + bk * 136 + bn) * 8;
    const unsigned bu_d = sm_u + (unsigned)(2 * F1_ASZ + 2 * F1_BSZ + bk * 136 + bn) * 8;

    const int w = tid >> 5, lane = tid & 31;
    const int wm = (w >> 1) * 32, wn = (w & 1) * 64;
    const int fr = lane >> 2, fc = lane & 3;

    float accG[2][8][4] = {}, accU[2][8][4] = {};

    const int KT = H_DIM / 16;  // 64
    // prefetch stage 0
    {
        cp16(a_d0, axr0); cp16(a_d0 + 16, axr0 + 2);
        cp16(a_d1, axr1); cp16(a_d1 + 16, axr1 + 2);
        #pragma unroll
        for (int j = 0; j < 4; j++) {
            cp16(bg_d + j * 16, bgp + j * 2);
            cp16(bu_d + j * 16, bup + j * 2);
        }
        CP_COMMIT();
    }

    for (int kt = 0; kt < KT; kt++) {
        if (kt + 1 < KT) {
            int k0 = (kt + 1) * 16;
            int st = (kt + 1) & 1;
            unsigned so = (unsigned)(st * F1_ASZ) * 8;
            unsigned sb = (unsigned)(st * F1_BSZ) * 8;
            cp16(a_d0 + so, axr0 + k0); cp16(a_d0 + so + 16, axr0 + k0 + 2);
            cp16(a_d1 + so, axr1 + k0); cp16(a_d1 + so + 16, axr1 + k0 + 2);
            const uint2* bg2 = bgp + (size_t)k0 * I_DIM;
            const uint2* bu2 = bup + (size_t)k0 * I_DIM;
            #pragma unroll
            for (int j = 0; j < 4; j++) {
                cp16(bg_d + sb + j * 16, bg2 + j * 2);
                cp16(bu_d + sb + j * 16, bu2 + j * 2);
            }
            CP_COMMIT();
            CP_WAIT1();
        } else {
            CP_WAIT0();
        }
        __syncthreads();
        const int st = kt & 1;
        const uint2* A  = As + st * F1_ASZ;
        const uint2* BG = Bg + st * F1_BSZ;
        const uint2* BU = Bu + st * F1_BSZ;
        #pragma unroll
        for (int kk = 0; kk < 16; kk += 8) {
            uint2 a[2][4];
            #pragma unroll
            for (int mi = 0; mi < 2; mi++) {
                int mb = wm + mi * 16 + fr;
                a[mi][0] = A[mb * 20 + kk + fc];
                a[mi][1] = A[(mb + 8) * 20 + kk + fc];
                a[mi][2] = A[mb * 20 + kk + fc + 4];
                a[mi][3] = A[(mb + 8) * 20 + kk + fc + 4];
            }
            #pragma unroll
            for (int nj = 0; nj < 8; nj++) {
                int nb = wn + nj * 8 + fr;
                uint2 b0 = BG[(kk + fc) * 136 + nb];
                uint2 b1 = BG[(kk + fc + 4) * 136 + nb];
                mma3(accG[0][nj], a[0], b0, b1);
                mma3(accG[1][nj], a[1], b0, b1);
                b0 = BU[(kk + fc) * 136 + nb];
                b1 = BU[(kk + fc + 4) * 136 + nb];
                mma3(accU[0][nj], a[0], b0, b1);
                mma3(accU[1][nj], a[1], b0, b1);
            }
        }
        __syncthreads();
    }

    // epilogue: silu(g)*u, split, write interleaved (hi,lo)
    #pragma unroll
    for (int mi = 0; mi < 2; mi++) {
        #pragma unroll
        for (int nj = 0; nj < 8; nj++) {
            int row = m0 + wm + mi * 16 + fr;
            int col = n0 + wn + nj * 8 + 2 * fc;
            if (row < cnt) {
                float g0 = accG[mi][nj][0], g1 = accG[mi][nj][1];
                float u0 = accU[mi][nj][0], u1 = accU[mi][nj][1];
                float h0 = g0 / (1.f + expf(-g0)) * u0;
                float h1 = g1 / (1.f + expf(-g1)) * u1;
                uint2 s0 = split2(h0), s1 = split2(h1);
                uint4 o; o.x = s0.x; o.y = s0.y; o.z = s1.x; o.w = s1.y;
                *(uint4*)&g_hdn_s[(size_t)(beg + row) * I_DIM + col] = o;
            }
            if (row + 8 < cnt) {
                float g0 = accG[mi][nj][2], g1 = accG[mi][nj][3];
                float u0 = accU[mi][nj][2], u1 = accU[mi][nj][3];
                float h0 = g0 / (1.f + expf(-g0)) * u0;
                float h1 = g1 / (1.f + expf(-g1)) * u1;
                uint2 s0 = split2(h0), s1 = split2(h1);
                uint4 o; o.x = s0.x; o.y = s0.y; o.z = s1.x; o.w = s1.y;
                *(uint4*)&g_hdn_s[(size_t)(beg + row + 8) * I_DIM + col] = o;
            }
        }
    }
}

// ---------------- GEMM2: pairout = (hdn @ wd[e]) * pairw ---------------------
// Block 128(M) x 128(N), KS=16. 8 warps 4(M)x2(N), warp tile 32x64.
#define F2_ASZ 2560
#define F2_BSZ 2176
__global__ void __launch_bounds__(256, 1) ffn2_kernel() {
    extern __shared__ uint2 sm2[];
    uint2* As = sm2;                    // [2][128][20]
    uint2* Bs = sm2 + 2 * F2_ASZ;       // [2][16][136]

    const int e = blockIdx.z;
    const int cnt = g_counts[e];
    const int m0 = blockIdx.x * 128;
    if (m0 >= cnt) return;
    const int beg = g_offsets[e];
    const int n0 = blockIdx.y * 128;

    const int tid = threadIdx.x;
    const int ar = tid >> 2;
    const int ac = (tid & 3) * 4;
    int r0 = m0 + ar;       if (r0 >= cnt) r0 = cnt - 1;
    int r1 = m0 + ar + 64;  if (r1 >= cnt) r1 = cnt - 1;
    const uint2* axr0 = g_hdn_s + (size_t)(beg + r0) * I_DIM + ac;
    const uint2* axr1 = g_hdn_s + (size_t)(beg + r1) * I_DIM + ac;
    const int bk = tid >> 4;
    const int bn = (tid & 15) * 8;
    const uint2* bp = g_wd_s + (size_t)e * I_DIM * H_DIM + (size_t)bk * H_DIM + n0 + bn;

    unsigned sm_u = (unsigned)__cvta_generic_to_shared(sm2);
    const unsigned a_d0 = sm_u + (unsigned)(ar * 20 + ac) * 8;
    const unsigned a_d1 = sm_u + (unsigned)((ar + 64) * 20 + ac) * 8;
    const unsigned b_d  = sm_u + (unsigned)(2 * F2_ASZ + bk * 136 + bn) * 8;

    const int w = tid >> 5, lane = tid & 31;
    const int wm = (w >> 1) * 32, wn = (w & 1) * 64;
    const int fr = lane >> 2, fc = lane & 3;

    float acc[2][8][4] = {};

    const int KT = I_DIM / 16;  // 256
    {
        cp16(a_d0, axr0); cp16(a_d0 + 16, axr0 + 2);
        cp16(a_d1, axr1); cp16(a_d1 + 16, axr1 + 2);
        #pragma unroll
        for (int j = 0; j < 4; j++) cp16(b_d + j * 16, bp + j * 2);
        CP_COMMIT();
    }

    for (int kt = 0; kt < KT; kt++) {
        if (kt + 1 < KT) {
            int k0 = (kt + 1) * 16;
            int st = (kt + 1) & 1;
            unsigned so = (unsigned)(st * F2_ASZ) * 8;
            unsigned sb = (unsigned)(st * F2_BSZ) * 8;
            cp16(a_d0 + so, axr0 + k0); cp16(a_d0 + so + 16, axr0 + k0 + 2);
            cp16(a_d1 + so, axr1 + k0); cp16(a_d1 + so + 16, axr1 + k0 + 2);
            const uint2* b2 = bp + (size_t)k0 * H_DIM;
            #pragma unroll
            for (int j = 0; j < 4; j++) cp16(b_d + sb + j * 16, b2 + j * 2);
            CP_COMMIT();
            CP_WAIT1();
        } else {
            CP_WAIT0();
        }
        __syncthreads();
        const int st = kt & 1;
        const uint2* A = As + st * F2_ASZ;
        const uint2* B = Bs + st * F2_BSZ;
        #pragma unroll
        for (int kk = 0; kk < 16; kk += 8) {
            uint2 a[2][4];
            #pragma unroll
            for (int mi = 0; mi < 2; mi++) {
                int mb = wm + mi * 16 + fr;
                a[mi][0] = A[mb * 20 + kk + fc];
                a[mi][1] = A[(mb + 8) * 20 + kk + fc];
                a[mi][2] = A[mb * 20 + kk + fc + 4];
                a[mi][3] = A[(mb + 8) * 20 + kk + fc + 4];
            }
            #pragma unroll
            for (int nj = 0; nj < 8; nj++) {
                int nb = wn + nj * 8 + fr;
                uint2 b0 = B[(kk + fc) * 136 + nb];
                uint2 b1 = B[(kk + fc + 4) * 136 + nb];
                mma3(acc[0][nj], a[0], b0, b1);
                mma3(acc[1][nj], a[1], b0, b1);
            }
        }
        __syncthreads();
    }

    #pragma unroll
    for (int mi = 0; mi < 2; mi++) {
        int row = m0 + wm + mi * 16 + fr;
        float pw0 = (row < cnt)     ? g_pairw[beg + row]     : 0.f;
        float pw8 = (row + 8 < cnt) ? g_pairw[beg + row + 8] : 0.f;
        #pragma unroll
        for (int nj = 0; nj < 8; nj++) {
            int col = n0 + wn + nj * 8 + 2 * fc;
            if (row < cnt) {
                float2 v = { acc[mi][nj][0] * pw0, acc[mi][nj][1] * pw0 };
                *(float2*)&g_pairout[(size_t)(beg + row) * H_DIM + col] = v;
            }
            if (row + 8 < cnt) {
                float2 v = { acc[mi][nj][2] * pw8, acc[mi][nj][3] * pw8 };
                *(float2*)&g_pairout[(size_t)(beg + row + 8) * H_DIM + col] = v;
            }
        }
    }
}

// ---------------- combine: out[t] = pairout[pos0] + pairout[pos1] ------------
__global__ void combine_kernel(float* __restrict__ out) {
    int idx = blockIdx.x * blockDim.x + threadIdx.x;
    if (idx >= T_TOK * H_DIM) return;
    int t = idx >> 10;
    int h = idx & (H_DIM - 1);
    int p0 = g_pos[t * 2 + 0], p1 = g_pos[t * 2 + 1];
    out[idx] = g_pairout[(size_t)p0 * H_DIM + h] + g_pairout[(size_t)p1 * H_DIM + h];
}

// ---------------- launcher ----------------------------------------------------
extern "C" void kernel_launch(void* const* d_in, const int* in_sizes, int n_in,
                              void* d_out, int out_size) {
    const float* x  = (const float*)d_in[0];
    const float* gw = (const float*)d_in[1];
    const float* wg = (const float*)d_in[2];
    const float* wu = (const float*)d_in[3];
    const float* wd = (const float*)d_in[4];
    float* out = (float*)d_out;

    cudaFuncSetAttribute(ffn1_kernel, cudaFuncAttributeMaxDynamicSharedMemorySize,
                         (2 * F1_ASZ + 4 * F1_BSZ) * 8);
    cudaFuncSetAttribute(ffn2_kernel, cudaFuncAttributeMaxDynamicSharedMemorySize,
                         (2 * F2_ASZ + 2 * F2_BSZ) * 8);

    zero_kernel<<<1, 32>>>();
    router_kernel<<<T_TOK, 256>>>(x, gw);
    int write_aux = (out_size > T_TOK * H_DIM) ? 1 : 0;
    finalize_router<<<1, 1>>>(out + (size_t)T_TOK * H_DIM, write_aux);
    scatter_kernel<<<(T_TOK + 255) / 256, 256>>>();

    // preprocess: split x + weights into (hi,lo) tf32 pairs
    uint2 *x_s, *wg_s, *wu_s, *wd_s;
    cudaGetSymbolAddress((void**)&x_s,  g_x_s);
    cudaGetSymbolAddress((void**)&wg_s, g_wg_s);
    cudaGetSymbolAddress((void**)&wu_s, g_wu_s);
    cudaGetSymbolAddress((void**)&wd_s, g_wd_s);
    long nw4 = (long)E_EXP * H_DIM * I_DIM / 4;
    split_kernel<<<2048, 256>>>(x,  x_s,  (long)T_TOK * H_DIM / 4);
    split_kernel<<<4096, 256>>>(wg, wg_s, nw4);
    split_kernel<<<4096, 256>>>(wu, wu_s, nw4);
    split_kernel<<<4096, 256>>>(wd, wd_s, nw4);

    dim3 g1(32, I_DIM / 128, E_EXP);
    ffn1_kernel<<<g1, 256, (2 * F1_ASZ + 4 * F1_BSZ) * 8>>>(x);
    dim3 g2(32, H_DIM / 128, E_EXP);
    ffn2_kernel<<<g2, 256, (2 * F2_ASZ + 2 * F2_BSZ) * 8>>>();

    combine_kernel<<<(T_TOK * H_DIM + 255) / 256, 256>>>(out);
}

// round 7
// speedup vs baseline: 2.1505x; 2.1505x over previous
#include <cuda_runtime.h>
#include <cuda_bf16.h>
#include <math.h>

// Problem constants
#define T_TOK 4096
#define H_DIM 1024
#define I_DIM 4096
#define E_EXP 8
#define K_TOP 2
#define P_PAIR (T_TOK * K_TOP)
#define HP (H_DIM / 2)   // k-pairs along H
#define IP (I_DIM / 2)   // k-pairs along I

// ---------------- scratch (static device globals; no runtime alloc) ----------
// bf16x3 split storage: one uint2 per k-PAIR of fp32 elements:
//   .x = bf16x2{hi(k_even) lo16bits, hi(k_odd) hi16bits}
//   .y = bf16x2{lo(k_even), lo(k_odd)}   (residuals)
// Footprint: 4 bytes per original fp32 element (same as fp32).
__device__ uint2 g_xs [(size_t)T_TOK * HP];            // 16.8 MB  [t][kp]
__device__ uint2 g_wgs[(size_t)E_EXP * HP * I_DIM];    // 134 MB   [e][kp][n]
__device__ uint2 g_wus[(size_t)E_EXP * HP * I_DIM];    // 134 MB
__device__ uint2 g_wds[(size_t)E_EXP * IP * H_DIM];    // 134 MB   [e][kp][n]
__device__ uint2 g_hdns[(size_t)P_PAIR * IP];          // 134 MB   [pair][kp]
__device__ float g_pairout[(size_t)P_PAIR * H_DIM];    // 33.5 MB
__device__ int   g_perm[P_PAIR];
__device__ float g_pairw[P_PAIR];
__device__ int   g_pos[P_PAIR];
__device__ int   g_tki[T_TOK * K_TOP];
__device__ float g_tkw[T_TOK * K_TOP];
__device__ int   g_counts[E_EXP];
__device__ int   g_offsets[E_EXP];
__device__ int   g_cursor[E_EXP];
__device__ float g_load[E_EXP];

// ---------------- bf16 split + mma helpers -----------------------------------
__device__ __forceinline__ uint2 split_pair(float e0, float e1) {
    __nv_bfloat16 h0 = __float2bfloat16_rn(e0);
    __nv_bfloat16 h1 = __float2bfloat16_rn(e1);
    float r0 = e0 - __bfloat162float(h0);
    float r1 = e1 - __bfloat162float(h1);
    __nv_bfloat16 l0 = __float2bfloat16_rn(r0);
    __nv_bfloat16 l1 = __float2bfloat16_rn(r1);
    uint2 o;
    o.x = (unsigned)__bfloat16_as_ushort(h0) | ((unsigned)__bfloat16_as_ushort(h1) << 16);
    o.y = (unsigned)__bfloat16_as_ushort(l0) | ((unsigned)__bfloat16_as_ushort(l1) << 16);
    return o;
}
__device__ __forceinline__ void mma16(float* c, unsigned a0, unsigned a1,
                                      unsigned a2, unsigned a3,
                                      unsigned b0, unsigned b1) {
    asm volatile(
        "mma.sync.aligned.m16n8k16.row.col.f32.bf16.bf16.f32 "
        "{%0,%1,%2,%3}, {%4,%5,%6,%7}, {%8,%9}, {%0,%1,%2,%3};"
        : "+f"(c[0]), "+f"(c[1]), "+f"(c[2]), "+f"(c[3])
        : "r"(a0), "r"(a1), "r"(a2), "r"(a3), "r"(b0), "r"(b1));
}
// 3-term: Ah*Bh + Al*Bh + Ah*Bl. a[j] = uint2{hi,lo}, b0/b1 = uint2{hi,lo}.
__device__ __forceinline__ void mma3(float* c, const uint2 a[4], uint2 b0, uint2 b1) {
    mma16(c, a[0].x, a[1].x, a[2].x, a[3].x, b0.x, b1.x);
    mma16(c, a[0].y, a[1].y, a[2].y, a[3].y, b0.x, b1.x);
    mma16(c, a[0].x, a[1].x, a[2].x, a[3].x, b0.y, b1.y);
}
__device__ __forceinline__ void cp16(unsigned dst, const void* src) {
    asm volatile("cp.async.cg.shared.global [%0], [%1], 16;" :: "r"(dst), "l"(src));
}
#define CP_COMMIT() asm volatile("cp.async.commit_group;")
#define CP_WAIT0()  asm volatile("cp.async.wait_group 0;")

// ---------------- small kernels ----------------------------------------------
__global__ void zero_kernel() {
    int i = threadIdx.x;
    if (i < E_EXP) { g_counts[i] = 0; g_load[i] = 0.f; }
}

__global__ void router_kernel(const float* __restrict__ x,
                              const float* __restrict__ gw) {
    int t = blockIdx.x;
    int w = threadIdx.x >> 5, lane = threadIdx.x & 31;
    __shared__ float logits[E_EXP];
    const float* xr = x + (size_t)t * H_DIM;
    float s = 0.f;
    for (int h = lane; h < H_DIM; h += 32)
        s += xr[h] * gw[h * E_EXP + w];
    #pragma unroll
    for (int o = 16; o; o >>= 1) s += __shfl_xor_sync(0xffffffffu, s, o);
    if (lane == 0) logits[w] = s;
    __syncthreads();
    if (threadIdx.x == 0) {
        float mx = logits[0];
        #pragma unroll
        for (int e = 1; e < E_EXP; e++) mx = fmaxf(mx, logits[e]);
        float p[E_EXP], den = 0.f;
        #pragma unroll
        for (int e = 0; e < E_EXP; e++) { p[e] = expf(logits[e] - mx); den += p[e]; }
        #pragma unroll
        for (int e = 0; e < E_EXP; e++) p[e] /= den;
        int i0 = 0;
        #pragma unroll
        for (int e = 1; e < E_EXP; e++) if (p[e] > p[i0]) i0 = e;
        int i1 = -1;
        #pragma unroll
        for (int e = 0; e < E_EXP; e++) {
            if (e == i0) continue;
            if (i1 < 0 || p[e] > p[i1]) i1 = e;
        }
        float w0 = p[i0], w1 = p[i1], sm = w0 + w1;
        g_tki[t * 2 + 0] = i0; g_tki[t * 2 + 1] = i1;
        g_tkw[t * 2 + 0] = w0 / sm; g_tkw[t * 2 + 1] = w1 / sm;
        atomicAdd(&g_counts[i0], 1); atomicAdd(&g_counts[i1], 1);
        atomicAdd(&g_load[i0], w0);  atomicAdd(&g_load[i1], w1);
    }
}

__global__ void finalize_router(float* out_aux, int write_aux) {
    if (threadIdx.x == 0) {
        int off = 0;
        for (int e = 0; e < E_EXP; e++) {
            g_offsets[e] = off; g_cursor[e] = off; off += g_counts[e];
        }
        if (write_aux) {
            float aux = 0.f;
            for (int e = 0; e < E_EXP; e++) {
                float Pe = g_load[e] / (float)T_TOK;
                float Pt = (float)g_counts[e] / (float)(T_TOK * K_TOP);
                aux += Pe * Pt;
            }
            *out_aux = aux * (float)E_EXP * 0.001f;
        }
    }
}

__global__ void scatter_kernel() {
    int t = blockIdx.x * blockDim.x + threadIdx.x;
    if (t >= T_TOK) return;
    #pragma unroll
    for (int k = 0; k < K_TOP; k++) {
        int e = g_tki[t * 2 + k];
        int p = atomicAdd(&g_cursor[e], 1);
        g_perm[p] = t;
        g_pairw[p] = g_tkw[t * 2 + k];
        g_pos[t * 2 + k] = p;
    }
}

// ---------------- preprocessing ----------------------------------------------
// x: pairs along contiguous dim. One float4 = 2 pairs = one uint4 out.
__global__ void split_x_kernel(const float* __restrict__ src,
                               uint2* __restrict__ dst, long n4) {
    long stride = (long)gridDim.x * blockDim.x;
    for (long i = (long)blockIdx.x * blockDim.x + threadIdx.x; i < n4; i += stride) {
        float4 v = ((const float4*)src)[i];
        uint2 p0 = split_pair(v.x, v.y);
        uint2 p1 = split_pair(v.z, v.w);
        uint4 o; o.x = p0.x; o.y = p0.y; o.z = p1.x; o.w = p1.y;
        ((uint4*)dst)[i] = o;
    }
}

// Weights: k runs along ROWS. Pair rows (2kp, 2kp+1); out[kp][n] = pair of column n.
// Rp = total row-pairs (E*R/2, pairs never cross experts since R even), C = columns.
__global__ void split_w_kernel(const float* __restrict__ src,
                               uint2* __restrict__ dst, long Rp, int C) {
    long total = Rp * (long)(C / 4);
    long stride = (long)gridDim.x * blockDim.x;
    int c4 = C / 4;
    for (long i = (long)blockIdx.x * blockDim.x + threadIdx.x; i < total; i += stride) {
        long kp = i / c4;
        int  n4 = (int)(i % c4) * 4;
        const float* r0 = src + (size_t)(2 * kp) * C + n4;
        float4 a = *(const float4*)r0;
        float4 b = *(const float4*)(r0 + C);
        uint2 p0 = split_pair(a.x, b.x);
        uint2 p1 = split_pair(a.y, b.y);
        uint2 p2 = split_pair(a.z, b.z);
        uint2 p3 = split_pair(a.w, b.w);
        uint2* dp = dst + (size_t)kp * C + n4;
        uint4 o0; o0.x = p0.x; o0.y = p0.y; o0.z = p1.x; o0.w = p1.y;
        uint4 o1; o1.x = p2.x; o1.y = p2.y; o1.z = p3.x; o1.w = p3.y;
        ((uint4*)dp)[0] = o0;
        ((uint4*)dp)[1] = o1;
    }
}

// ---------------- GEMM1: hdn = silu(X@wg[e]) * (X@wu[e]) ---------------------
// Block 128M x 64N, 8 warps 4mx2n, warp tile 32x32 for G and U.
// One k16 chunk per stage (8 pairs). Double-buffered cp.async, 1 sync/iter.
__global__ void __launch_bounds__(256) ffn1_kernel() {
    __shared__ __align__(16) uint2 As[2][128][12];  // pairs 0..7 + pad
    __shared__ __align__(16) uint2 Bg[2][8][68];    // [kp][n] + pad
    __shared__ __align__(16) uint2 Bu[2][8][68];
    __shared__ int perm_s[128];

    const int e = blockIdx.z;
    const int cnt = g_counts[e];
    const int m0 = blockIdx.x * 128;
    if (m0 >= cnt) return;
    const int beg = g_offsets[e];
    const int n0 = blockIdx.y * 64;
    const int tid = threadIdx.x;

    if (tid < 128) {
        int r = m0 + tid;
        perm_s[tid] = g_perm[beg + (r < cnt ? r : cnt - 1)];
    }
    __syncthreads();

    // copy mappings
    const int ar  = tid >> 1;            // row 0..127
    const int apb = (tid & 1) * 4;       // pair 0 or 4
    const uint2* axr = g_xs + (size_t)perm_s[ar] * HP + apb;
    const int bkp = tid >> 5;            // 0..7
    const int bn  = (tid & 31) * 2;      // 0..62
    const size_t eoffB = (size_t)e * HP * I_DIM;
    const uint2* bgp = g_wgs + eoffB + (size_t)bkp * I_DIM + n0 + bn;
    const uint2* bup = g_wus + eoffB + (size_t)bkp * I_DIM + n0 + bn;

    const unsigned a_sm = (unsigned)__cvta_generic_to_shared(&As[0][ar][apb]);
    const unsigned g_sm = (unsigned)__cvta_generic_to_shared(&Bg[0][bkp][bn]);
    const unsigned u_sm = (unsigned)__cvta_generic_to_shared(&Bu[0][bkp][bn]);
    const unsigned ASTG = 128 * 12 * 8;
    const unsigned BSTG = 8 * 68 * 8;

    const int w = tid >> 5, lane = tid & 31;
    const int wm = (w >> 1) * 32, wn = (w & 1) * 32;
    const int fr = lane >> 2, fc = lane & 3;

    float accG[2][4][4] = {}, accU[2][4][4] = {};

    const int KT = HP / 8;  // 64
    // prefetch kt=0
    cp16(a_sm, axr); cp16(a_sm + 16, axr + 2);
    cp16(g_sm, bgp); cp16(u_sm, bup);
    CP_COMMIT();

    for (int kt = 0; kt < KT; kt++) {
        CP_WAIT0();          // stage kt landed (pending group is only stage kt)
        __syncthreads();     // all warps see it; all done reading the other buf
        if (kt + 1 < KT) {
            const int sn = (kt + 1) & 1;
            const uint2* a2 = axr + (kt + 1) * 8;
            cp16(a_sm + sn * ASTG, a2); cp16(a_sm + sn * ASTG + 16, a2 + 2);
            cp16(g_sm + sn * BSTG, bgp + (size_t)(kt + 1) * 8 * I_DIM);
            cp16(u_sm + sn * BSTG, bup + (size_t)(kt + 1) * 8 * I_DIM);
            CP_COMMIT();
        }
        const int st = kt & 1;
        uint2 a[2][4];
        #pragma unroll
        for (int mi = 0; mi < 2; mi++) {
            int mr = wm + mi * 16 + fr;
            a[mi][0] = As[st][mr][fc];
            a[mi][1] = As[st][mr + 8][fc];
            a[mi][2] = As[st][mr][fc + 4];
            a[mi][3] = As[st][mr + 8][fc + 4];
        }
        #pragma unroll
        for (int nj = 0; nj < 4; nj++) {
            int nb = wn + nj * 8 + fr;
            uint2 b0 = Bg[st][fc][nb], b1 = Bg[st][fc + 4][nb];
            mma3(accG[0][nj], a[0], b0, b1);
            mma3(accG[1][nj], a[1], b0, b1);
            b0 = Bu[st][fc][nb]; b1 = Bu[st][fc + 4][nb];
            mma3(accU[0][nj], a[0], b0, b1);
            mma3(accU[1][nj], a[1], b0, b1);
        }
    }

    // epilogue: silu(g)*u, write hdn already split (pair format for GEMM2)
    #pragma unroll
    for (int mi = 0; mi < 2; mi++) {
        #pragma unroll
        for (int nj = 0; nj < 4; nj++) {
            int row = m0 + wm + mi * 16 + fr;
            int pr  = (n0 + wn + nj * 8 + 2 * fc) >> 1;   // k-pair index in I
            if (row < cnt) {
                float g0 = accG[mi][nj][0], g1 = accG[mi][nj][1];
                float u0 = accU[mi][nj][0], u1 = accU[mi][nj][1];
                float h0 = g0 / (1.f + expf(-g0)) * u0;
                float h1 = g1 / (1.f + expf(-g1)) * u1;
                g_hdns[(size_t)(beg + row) * IP + pr] = split_pair(h0, h1);
            }
            if (row + 8 < cnt) {
                float g0 = accG[mi][nj][2], g1 = accG[mi][nj][3];
                float u0 = accU[mi][nj][2], u1 = accU[mi][nj][3];
                float h0 = g0 / (1.f + expf(-g0)) * u0;
                float h1 = g1 / (1.f + expf(-g1)) * u1;
                g_hdns[(size_t)(beg + row + 8) * IP + pr] = split_pair(h0, h1);
            }
        }
    }
}

// ---------------- GEMM2: pairout = (hdn @ wd[e]) * pairw ---------------------
// Block 128M x 128N, 8 warps 4mx2n, warp tile 32x64.
__global__ void __launch_bounds__(256) ffn2_kernel() {
    __shared__ __align__(16) uint2 As[2][128][12];
    __shared__ __align__(16) uint2 Bs[2][8][132];

    const int e = blockIdx.z;
    const int cnt = g_counts[e];
    const int m0 = blockIdx.x * 128;
    if (m0 >= cnt) return;
    const int beg = g_offsets[e];
    const int n0 = blockIdx.y * 128;
    const int tid = threadIdx.x;

    const int ar  = tid >> 1;
    const int apb = (tid & 1) * 4;
    int rr = m0 + ar; if (rr >= cnt) rr = cnt - 1;
    const uint2* axr = g_hdns + (size_t)(beg + rr) * IP + apb;
    const int bkp = tid >> 5;            // 0..7
    const int bn4 = (tid & 31) * 4;      // 0..124
    const uint2* bp = g_wds + ((size_t)e * IP + bkp) * H_DIM + n0 + bn4;

    const unsigned a_sm = (unsigned)__cvta_generic_to_shared(&As[0][ar][apb]);
    const unsigned b_sm = (unsigned)__cvta_generic_to_shared(&Bs[0][bkp][bn4]);
    const unsigned ASTG = 128 * 12 * 8;
    const unsigned BSTG = 8 * 132 * 8;

    const int w = tid >> 5, lane = tid & 31;
    const int wm = (w >> 1) * 32, wn = (w & 1) * 64;
    const int fr = lane >> 2, fc = lane & 3;

    float acc[2][8][4] = {};

    const int KT = IP / 8;  // 256
    cp16(a_sm, axr); cp16(a_sm + 16, axr + 2);
    cp16(b_sm, bp);  cp16(b_sm + 16, bp + 2);
    CP_COMMIT();

    for (int kt = 0; kt < KT; kt++) {
        CP_WAIT0();
        __syncthreads();
        if (kt + 1 < KT) {
            const int sn = (kt + 1) & 1;
            const uint2* a2 = axr + (kt + 1) * 8;
            const uint2* b2 = bp + (size_t)(kt + 1) * 8 * H_DIM;
            cp16(a_sm + sn * ASTG, a2); cp16(a_sm + sn * ASTG + 16, a2 + 2);
            cp16(b_sm + sn * BSTG, b2); cp16(b_sm + sn * BSTG + 16, b2 + 2);
            CP_COMMIT();
        }
        const int st = kt & 1;
        uint2 a[2][4];
        #pragma unroll
        for (int mi = 0; mi < 2; mi++) {
            int mr = wm + mi * 16 + fr;
            a[mi][0] = As[st][mr][fc];
            a[mi][1] = As[st][mr + 8][fc];
            a[mi][2] = As[st][mr][fc + 4];
            a[mi][3] = As[st][mr + 8][fc + 4];
        }
        #pragma unroll
        for (int nj = 0; nj < 8; nj++) {
            int nb = wn + nj * 8 + fr;
            uint2 b0 = Bs[st][fc][nb], b1 = Bs[st][fc + 4][nb];
            mma3(acc[0][nj], a[0], b0, b1);
            mma3(acc[1][nj], a[1], b0, b1);
        }
    }

    #pragma unroll
    for (int mi = 0; mi < 2; mi++) {
        int row = m0 + wm + mi * 16 + fr;
        float pw0 = (row < cnt)     ? g_pairw[beg + row]     : 0.f;
        float pw8 = (row + 8 < cnt) ? g_pairw[beg + row + 8] : 0.f;
        #pragma unroll
        for (int nj = 0; nj < 8; nj++) {
            int col = n0 + wn + nj * 8 + 2 * fc;
            if (row < cnt) {
                float2 v = { acc[mi][nj][0] * pw0, acc[mi][nj][1] * pw0 };
                *(float2*)&g_pairout[(size_t)(beg + row) * H_DIM + col] = v;
            }
            if (row + 8 < cnt) {
                float2 v = { acc[mi][nj][2] * pw8, acc[mi][nj][3] * pw8 };
                *(float2*)&g_pairout[(size_t)(beg + row + 8) * H_DIM + col] = v;
            }
        }
    }
}

// ---------------- combine: out[t] = pairout[pos0] + pairout[pos1] ------------
__global__ void combine_kernel(float* __restrict__ out) {
    int idx = blockIdx.x * blockDim.x + threadIdx.x;
    if (idx >= T_TOK * H_DIM) return;
    int t = idx >> 10;
    int h = idx & (H_DIM - 1);
    int p0 = g_pos[t * 2 + 0], p1 = g_pos[t * 2 + 1];
    out[idx] = g_pairout[(size_t)p0 * H_DIM + h] + g_pairout[(size_t)p1 * H_DIM + h];
}

// ---------------- launcher ----------------------------------------------------
extern "C" void kernel_launch(void* const* d_in, const int* in_sizes, int n_in,
                              void* d_out, int out_size) {
    const float* x  = (const float*)d_in[0];
    const float* gw = (const float*)d_in[1];
    const float* wg = (const float*)d_in[2];
    const float* wu = (const float*)d_in[3];
    const float* wd = (const float*)d_in[4];
    float* out = (float*)d_out;

    zero_kernel<<<1, 32>>>();
    router_kernel<<<T_TOK, 256>>>(x, gw);
    int write_aux = (out_size > T_TOK * H_DIM) ? 1 : 0;
    finalize_router<<<1, 1>>>(out + (size_t)T_TOK * H_DIM, write_aux);
    scatter_kernel<<<(T_TOK + 255) / 256, 256>>>();

    uint2 *xs, *wgs, *wus, *wds;
    cudaGetSymbolAddress((void**)&xs,  g_xs);
    cudaGetSymbolAddress((void**)&wgs, g_wgs);
    cudaGetSymbolAddress((void**)&wus, g_wus);
    cudaGetSymbolAddress((void**)&wds, g_wds);

    split_x_kernel<<<2048, 256>>>(x, xs, (long)T_TOK * H_DIM / 4);
    split_w_kernel<<<8192, 256>>>(wg, wgs, (long)E_EXP * HP, I_DIM);
    split_w_kernel<<<8192, 256>>>(wu, wus, (long)E_EXP * HP, I_DIM);
    split_w_kernel<<<8192, 256>>>(wd, wds, (long)E_EXP * IP, H_DIM);

    dim3 g1(T_TOK / 128, I_DIM / 64, E_EXP);   // (m-tiles, n-tiles, experts)
    ffn1_kernel<<<g1, 256>>>();
    dim3 g2(T_TOK / 128, H_DIM / 128, E_EXP);
    ffn2_kernel<<<g2, 256>>>();

    combine_kernel<<<(T_TOK * H_DIM + 255) / 256, 256>>>(out);
}

// round 8
// speedup vs baseline: 2.1959x; 1.0211x over previous
#include <cuda_runtime.h>
#include <cuda_bf16.h>
#include <math.h>

// Problem constants
#define T_TOK 4096
#define H_DIM 1024
#define I_DIM 4096
#define E_EXP 8
#define K_TOP 2
#define P_PAIR (T_TOK * K_TOP)
#define HP (H_DIM / 2)   // k-pairs along H
#define IP (I_DIM / 2)   // k-pairs along I

// ---------------- scratch (static device globals; no runtime alloc) ----------
// bf16x3 split storage: one uint2 per k-PAIR of fp32 elements:
//   .x = bf16x2{hi(k_even), hi(k_odd)}
//   .y = bf16x2{lo(k_even), lo(k_odd)}   (residuals)
__device__ uint2 g_xs [(size_t)T_TOK * HP];
__device__ uint2 g_wgs[(size_t)E_EXP * HP * I_DIM];
__device__ uint2 g_wus[(size_t)E_EXP * HP * I_DIM];
__device__ uint2 g_wds[(size_t)E_EXP * IP * H_DIM];
__device__ uint2 g_hdns[(size_t)P_PAIR * IP];
__device__ float g_pairout[(size_t)P_PAIR * H_DIM];
__device__ int   g_perm[P_PAIR];
__device__ float g_pairw[P_PAIR];
__device__ int   g_pos[P_PAIR];
__device__ int   g_tki[T_TOK * K_TOP];
__device__ float g_tkw[T_TOK * K_TOP];
__device__ int   g_counts[E_EXP];
__device__ int   g_offsets[E_EXP];
__device__ int   g_cursor[E_EXP];
__device__ float g_load[E_EXP];

// ---------------- bf16 split + mma helpers -----------------------------------
__device__ __forceinline__ uint2 split_pair(float e0, float e1) {
    __nv_bfloat16 h0 = __float2bfloat16_rn(e0);
    __nv_bfloat16 h1 = __float2bfloat16_rn(e1);
    float r0 = e0 - __bfloat162float(h0);
    float r1 = e1 - __bfloat162float(h1);
    __nv_bfloat16 l0 = __float2bfloat16_rn(r0);
    __nv_bfloat16 l1 = __float2bfloat16_rn(r1);
    uint2 o;
    o.x = (unsigned)__bfloat16_as_ushort(h0) | ((unsigned)__bfloat16_as_ushort(h1) << 16);
    o.y = (unsigned)__bfloat16_as_ushort(l0) | ((unsigned)__bfloat16_as_ushort(l1) << 16);
    return o;
}
__device__ __forceinline__ void mma16(float* c, unsigned a0, unsigned a1,
                                      unsigned a2, unsigned a3,
                                      unsigned b0, unsigned b1) {
    asm volatile(
        "mma.sync.aligned.m16n8k16.row.col.f32.bf16.bf16.f32 "
        "{%0,%1,%2,%3}, {%4,%5,%6,%7}, {%8,%9}, {%0,%1,%2,%3};"
        : "+f"(c[0]), "+f"(c[1]), "+f"(c[2]), "+f"(c[3])
        : "r"(a0), "r"(a1), "r"(a2), "r"(a3), "r"(b0), "r"(b1));
}
__device__ __forceinline__ void mma3(float* c, const uint2 a[4], uint2 b0, uint2 b1) {
    mma16(c, a[0].x, a[1].x, a[2].x, a[3].x, b0.x, b1.x);
    mma16(c, a[0].y, a[1].y, a[2].y, a[3].y, b0.x, b1.x);
    mma16(c, a[0].x, a[1].x, a[2].x, a[3].x, b0.y, b1.y);
}
__device__ __forceinline__ void cp16(unsigned dst, const void* src) {
    asm volatile("cp.async.cg.shared.global [%0], [%1], 16;" :: "r"(dst), "l"(src));
}
#define CP_COMMIT() asm volatile("cp.async.commit_group;")
#define CP_WAIT(n)  asm volatile("cp.async.wait_group %0;" :: "n"(n))

// ---------------- small kernels ----------------------------------------------
__global__ void zero_kernel() {
    int i = threadIdx.x;
    if (i < E_EXP) { g_counts[i] = 0; g_load[i] = 0.f; }
}

__global__ void router_kernel(const float* __restrict__ x,
                              const float* __restrict__ gw) {
    int t = blockIdx.x;
    int w = threadIdx.x >> 5, lane = threadIdx.x & 31;
    __shared__ float logits[E_EXP];
    const float* xr = x + (size_t)t * H_DIM;
    float s = 0.f;
    for (int h = lane; h < H_DIM; h += 32)
        s += xr[h] * gw[h * E_EXP + w];
    #pragma unroll
    for (int o = 16; o; o >>= 1) s += __shfl_xor_sync(0xffffffffu, s, o);
    if (lane == 0) logits[w] = s;
    __syncthreads();
    if (threadIdx.x == 0) {
        float mx = logits[0];
        #pragma unroll
        for (int e = 1; e < E_EXP; e++) mx = fmaxf(mx, logits[e]);
        float p[E_EXP], den = 0.f;
        #pragma unroll
        for (int e = 0; e < E_EXP; e++) { p[e] = expf(logits[e] - mx); den += p[e]; }
        #pragma unroll
        for (int e = 0; e < E_EXP; e++) p[e] /= den;
        int i0 = 0;
        #pragma unroll
        for (int e = 1; e < E_EXP; e++) if (p[e] > p[i0]) i0 = e;
        int i1 = -1;
        #pragma unroll
        for (int e = 0; e < E_EXP; e++) {
            if (e == i0) continue;
            if (i1 < 0 || p[e] > p[i1]) i1 = e;
        }
        float w0 = p[i0], w1 = p[i1], sm = w0 + w1;
        g_tki[t * 2 + 0] = i0; g_tki[t * 2 + 1] = i1;
        g_tkw[t * 2 + 0] = w0 / sm; g_tkw[t * 2 + 1] = w1 / sm;
        atomicAdd(&g_counts[i0], 1); atomicAdd(&g_counts[i1], 1);
        atomicAdd(&g_load[i0], w0);  atomicAdd(&g_load[i1], w1);
    }
}

__global__ void finalize_router(float* out_aux, int write_aux) {
    if (threadIdx.x == 0) {
        int off = 0;
        for (int e = 0; e < E_EXP; e++) {
            g_offsets[e] = off; g_cursor[e] = off; off += g_counts[e];
        }
        if (write_aux) {
            float aux = 0.f;
            for (int e = 0; e < E_EXP; e++) {
                float Pe = g_load[e] / (float)T_TOK;
                float Pt = (float)g_counts[e] / (float)(T_TOK * K_TOP);
                aux += Pe * Pt;
            }
            *out_aux = aux * (float)E_EXP * 0.001f;
        }
    }
}

__global__ void scatter_kernel() {
    int t = blockIdx.x * blockDim.x + threadIdx.x;
    if (t >= T_TOK) return;
    #pragma unroll
    for (int k = 0; k < K_TOP; k++) {
        int e = g_tki[t * 2 + k];
        int p = atomicAdd(&g_cursor[e], 1);
        g_perm[p] = t;
        g_pairw[p] = g_tkw[t * 2 + k];
        g_pos[t * 2 + k] = p;
    }
}

// ---------------- preprocessing ----------------------------------------------
__global__ void split_x_kernel(const float* __restrict__ src,
                               uint2* __restrict__ dst, long n4) {
    long stride = (long)gridDim.x * blockDim.x;
    for (long i = (long)blockIdx.x * blockDim.x + threadIdx.x; i < n4; i += stride) {
        float4 v = ((const float4*)src)[i];
        uint2 p0 = split_pair(v.x, v.y);
        uint2 p1 = split_pair(v.z, v.w);
        uint4 o; o.x = p0.x; o.y = p0.y; o.z = p1.x; o.w = p1.y;
        ((uint4*)dst)[i] = o;
    }
}

__global__ void split_w_kernel(const float* __restrict__ src,
                               uint2* __restrict__ dst, long Rp, int C) {
    long total = Rp * (long)(C / 4);
    long stride = (long)gridDim.x * blockDim.x;
    int c4 = C / 4;
    for (long i = (long)blockIdx.x * blockDim.x + threadIdx.x; i < total; i += stride) {
        long kp = i / c4;
        int  n4 = (int)(i % c4) * 4;
        const float* r0 = src + (size_t)(2 * kp) * C + n4;
        float4 a = *(const float4*)r0;
        float4 b = *(const float4*)(r0 + C);
        uint2 p0 = split_pair(a.x, b.x);
        uint2 p1 = split_pair(a.y, b.y);
        uint2 p2 = split_pair(a.z, b.z);
        uint2 p3 = split_pair(a.w, b.w);
        uint2* dp = dst + (size_t)kp * C + n4;
        uint4 o0; o0.x = p0.x; o0.y = p0.y; o0.z = p1.x; o0.w = p1.y;
        uint4 o1; o1.x = p2.x; o1.y = p2.y; o1.z = p3.x; o1.w = p3.y;
        ((uint4*)dp)[0] = o0;
        ((uint4*)dp)[1] = o1;
    }
}

// ---------------- GEMM1: hdn = silu(X@wg[e]) * (X@wu[e]) ---------------------
// Block 128M x 64N, 8 warps 4mx2n, warp tile 32x32 for G and U.
// 4-stage cp.async ring, k16 per stage (8 pairs). One sync/iter.
#define F1_AS 1536          // 128*12 uint2
#define F1_BS 544           // 8*68 uint2
#define F1_STG (F1_AS + 2 * F1_BS)   // 2624 uint2 = 20992 B per stage
__global__ void __launch_bounds__(256) ffn1_kernel() {
    extern __shared__ __align__(16) uint2 dsm[];
    __shared__ int perm_s[128];

    const int e = blockIdx.z;
    const int cnt = g_counts[e];
    const int m0 = blockIdx.x * 128;
    if (m0 >= cnt) return;
    const int beg = g_offsets[e];
    const int n0 = blockIdx.y * 64;
    const int tid = threadIdx.x;

    if (tid < 128) {
        int r = m0 + tid;
        perm_s[tid] = g_perm[beg + (r < cnt ? r : cnt - 1)];
    }
    __syncthreads();

    const int ar  = tid >> 1;
    const int apb = (tid & 1) * 4;
    const uint2* axr = g_xs + (size_t)perm_s[ar] * HP + apb;
    const int bkp = tid >> 5;
    const int bn  = (tid & 31) * 2;
    const size_t eoffB = (size_t)e * HP * I_DIM;
    const uint2* bgp = g_wgs + eoffB + (size_t)bkp * I_DIM + n0 + bn;
    const uint2* bup = g_wus + eoffB + (size_t)bkp * I_DIM + n0 + bn;

    const unsigned sm0 = (unsigned)__cvta_generic_to_shared(dsm);
    const unsigned a_sm = sm0 + (unsigned)(ar * 12 + apb) * 8;
    const unsigned g_sm = sm0 + (unsigned)(F1_AS + bkp * 68 + bn) * 8;
    const unsigned u_sm = sm0 + (unsigned)(F1_AS + F1_BS + bkp * 68 + bn) * 8;
    const unsigned STGB = F1_STG * 8;

    const int w = tid >> 5, lane = tid & 31;
    const int wm = (w >> 1) * 32, wn = (w & 1) * 32;
    const int fr = lane >> 2, fc = lane & 3;

    float accG[2][4][4] = {}, accU[2][4][4] = {};

    const int KT = HP / 8;  // 64
    // prologue: fill stages 0..2
    #pragma unroll
    for (int s = 0; s < 3; s++) {
        const uint2* a2 = axr + s * 8;
        cp16(a_sm + s * STGB, a2); cp16(a_sm + s * STGB + 16, a2 + 2);
        cp16(g_sm + s * STGB, bgp + (size_t)s * 8 * I_DIM);
        cp16(u_sm + s * STGB, bup + (size_t)s * 8 * I_DIM);
        CP_COMMIT();
    }

    for (int kt = 0; kt < KT; kt++) {
        CP_WAIT(2);          // stage kt landed
        __syncthreads();     // visible to all; all warps done with stage kt-1
        const int pf = kt + 3;
        if (pf < KT) {
            const unsigned so = (unsigned)(pf & 3) * STGB;
            const uint2* a2 = axr + pf * 8;
            cp16(a_sm + so, a2); cp16(a_sm + so + 16, a2 + 2);
            cp16(g_sm + so, bgp + (size_t)pf * 8 * I_DIM);
            cp16(u_sm + so, bup + (size_t)pf * 8 * I_DIM);
        }
        CP_COMMIT();         // keep group count aligned (empty near tail)

        const uint2* A  = dsm + (kt & 3) * F1_STG;
        const uint2* BG = A + F1_AS;
        const uint2* BU = BG + F1_BS;
        uint2 a[2][4];
        #pragma unroll
        for (int mi = 0; mi < 2; mi++) {
            int mr = wm + mi * 16 + fr;
            a[mi][0] = A[mr * 12 + fc];
            a[mi][1] = A[(mr + 8) * 12 + fc];
            a[mi][2] = A[mr * 12 + fc + 4];
            a[mi][3] = A[(mr + 8) * 12 + fc + 4];
        }
        #pragma unroll
        for (int nj = 0; nj < 4; nj++) {
            int nb = wn + nj * 8 + fr;
            uint2 b0 = BG[fc * 68 + nb], b1 = BG[(fc + 4) * 68 + nb];
            mma3(accG[0][nj], a[0], b0, b1);
            mma3(accG[1][nj], a[1], b0, b1);
            b0 = BU[fc * 68 + nb]; b1 = BU[(fc + 4) * 68 + nb];
            mma3(accU[0][nj], a[0], b0, b1);
            mma3(accU[1][nj], a[1], b0, b1);
        }
    }

    #pragma unroll
    for (int mi = 0; mi < 2; mi++) {
        #pragma unroll
        for (int nj = 0; nj < 4; nj++) {
            int row = m0 + wm + mi * 16 + fr;
            int pr  = (n0 + wn + nj * 8 + 2 * fc) >> 1;
            if (row < cnt) {
                float g0 = accG[mi][nj][0], g1 = accG[mi][nj][1];
                float u0 = accU[mi][nj][0], u1 = accU[mi][nj][1];
                float h0 = g0 / (1.f + expf(-g0)) * u0;
                float h1 = g1 / (1.f + expf(-g1)) * u1;
                g_hdns[(size_t)(beg + row) * IP + pr] = split_pair(h0, h1);
            }
            if (row + 8 < cnt) {
                float g0 = accG[mi][nj][2], g1 = accG[mi][nj][3];
                float u0 = accU[mi][nj][2], u1 = accU[mi][nj][3];
                float h0 = g0 / (1.f + expf(-g0)) * u0;
                float h1 = g1 / (1.f + expf(-g1)) * u1;
                g_hdns[(size_t)(beg + row + 8) * IP + pr] = split_pair(h0, h1);
            }
        }
    }
}

// ---------------- GEMM2: pairout = (hdn @ wd[e]) * pairw ---------------------
// Block 128M x 128N, 8 warps 4mx2n, warp tile 32x64. 4-stage ring.
#define F2_AS 1536
#define F2_BS 1056          // 8*132 uint2
#define F2_STG (F2_AS + F2_BS)    // 2592 uint2 = 20736 B
__global__ void __launch_bounds__(256) ffn2_kernel() {
    extern __shared__ __align__(16) uint2 dsm2[];

    const int e = blockIdx.z;
    const int cnt = g_counts[e];
    const int m0 = blockIdx.x * 128;
    if (m0 >= cnt) return;
    const int beg = g_offsets[e];
    const int n0 = blockIdx.y * 128;
    const int tid = threadIdx.x;

    const int ar  = tid >> 1;
    const int apb = (tid & 1) * 4;
    int rr = m0 + ar; if (rr >= cnt) rr = cnt - 1;
    const uint2* axr = g_hdns + (size_t)(beg + rr) * IP + apb;
    const int bkp = tid >> 5;
    const int bn4 = (tid & 31) * 4;
    const uint2* bp = g_wds + ((size_t)e * IP + bkp) * H_DIM + n0 + bn4;

    const unsigned sm0 = (unsigned)__cvta_generic_to_shared(dsm2);
    const unsigned a_sm = sm0 + (unsigned)(ar * 12 + apb) * 8;
    const unsigned b_sm = sm0 + (unsigned)(F2_AS + bkp * 132 + bn4) * 8;
    const unsigned STGB = F2_STG * 8;

    const int w = tid >> 5, lane = tid & 31;
    const int wm = (w >> 1) * 32, wn = (w & 1) * 64;
    const int fr = lane >> 2, fc = lane & 3;

    float acc[2][8][4] = {};

    const int KT = IP / 8;  // 256
    #pragma unroll
    for (int s = 0; s < 3; s++) {
        const uint2* a2 = axr + s * 8;
        const uint2* b2 = bp + (size_t)s * 8 * H_DIM;
        cp16(a_sm + s * STGB, a2); cp16(a_sm + s * STGB + 16, a2 + 2);
        cp16(b_sm + s * STGB, b2); cp16(b_sm + s * STGB + 16, b2 + 2);
        CP_COMMIT();
    }

    for (int kt = 0; kt < KT; kt++) {
        CP_WAIT(2);
        __syncthreads();
        const int pf = kt + 3;
        if (pf < KT) {
            const unsigned so = (unsigned)(pf & 3) * STGB;
            const uint2* a2 = axr + pf * 8;
            const uint2* b2 = bp + (size_t)pf * 8 * H_DIM;
            cp16(a_sm + so, a2); cp16(a_sm + so + 16, a2 + 2);
            cp16(b_sm + so, b2); cp16(b_sm + so + 16, b2 + 2);
        }
        CP_COMMIT();

        const uint2* A = dsm2 + (kt & 3) * F2_STG;
        const uint2* B = A + F2_AS;
        uint2 a[2][4];
        #pragma unroll
        for (int mi = 0; mi < 2; mi++) {
            int mr = wm + mi * 16 + fr;
            a[mi][0] = A[mr * 12 + fc];
            a[mi][1] = A[(mr + 8) * 12 + fc];
            a[mi][2] = A[mr * 12 + fc + 4];
            a[mi][3] = A[(mr + 8) * 12 + fc + 4];
        }
        #pragma unroll
        for (int nj = 0; nj < 8; nj++) {
            int nb = wn + nj * 8 + fr;
            uint2 b0 = B[fc * 132 + nb], b1 = B[(fc + 4) * 132 + nb];
            mma3(acc[0][nj], a[0], b0, b1);
            mma3(acc[1][nj], a[1], b0, b1);
        }
    }

    #pragma unroll
    for (int mi = 0; mi < 2; mi++) {
        int row = m0 + wm + mi * 16 + fr;
        float pw0 = (row < cnt)     ? g_pairw[beg + row]     : 0.f;
        float pw8 = (row + 8 < cnt) ? g_pairw[beg + row + 8] : 0.f;
        #pragma unroll
        for (int nj = 0; nj < 8; nj++) {
            int col = n0 + wn + nj * 8 + 2 * fc;
            if (row < cnt) {
                float2 v = { acc[mi][nj][0] * pw0, acc[mi][nj][1] * pw0 };
                *(float2*)&g_pairout[(size_t)(beg + row) * H_DIM + col] = v;
            }
            if (row + 8 < cnt) {
                float2 v = { acc[mi][nj][2] * pw8, acc[mi][nj][3] * pw8 };
                *(float2*)&g_pairout[(size_t)(beg + row + 8) * H_DIM + col] = v;
            }
        }
    }
}

// ---------------- combine ------------------------------------------------------
__global__ void combine_kernel(float* __restrict__ out) {
    int idx = blockIdx.x * blockDim.x + threadIdx.x;
    if (idx >= T_TOK * H_DIM) return;
    int t = idx >> 10;
    int h = idx & (H_DIM - 1);
    int p0 = g_pos[t * 2 + 0], p1 = g_pos[t * 2 + 1];
    out[idx] = g_pairout[(size_t)p0 * H_DIM + h] + g_pairout[(size_t)p1 * H_DIM + h];
}

// ---------------- launcher ----------------------------------------------------
extern "C" void kernel_launch(void* const* d_in, const int* in_sizes, int n_in,
                              void* d_out, int out_size) {
    const float* x  = (const float*)d_in[0];
    const float* gw = (const float*)d_in[1];
    const float* wg = (const float*)d_in[2];
    const float* wu = (const float*)d_in[3];
    const float* wd = (const float*)d_in[4];
    float* out = (float*)d_out;

    static int attr_set = 0;
    if (!attr_set) {
        cudaFuncSetAttribute(ffn1_kernel, cudaFuncAttributeMaxDynamicSharedMemorySize,
                             4 * F1_STG * 8);
        cudaFuncSetAttribute(ffn2_kernel, cudaFuncAttributeMaxDynamicSharedMemorySize,
                             4 * F2_STG * 8);
        attr_set = 1;
    }

    zero_kernel<<<1, 32>>>();
    router_kernel<<<T_TOK, 256>>>(x, gw);
    int write_aux = (out_size > T_TOK * H_DIM) ? 1 : 0;
    finalize_router<<<1, 1>>>(out + (size_t)T_TOK * H_DIM, write_aux);
    scatter_kernel<<<(T_TOK + 255) / 256, 256>>>();

    uint2 *xs, *wgs, *wus, *wds;
    cudaGetSymbolAddress((void**)&xs,  g_xs);
    cudaGetSymbolAddress((void**)&wgs, g_wgs);
    cudaGetSymbolAddress((void**)&wus, g_wus);
    cudaGetSymbolAddress((void**)&wds, g_wds);

    split_x_kernel<<<2048, 256>>>(x, xs, (long)T_TOK * H_DIM / 4);
    split_w_kernel<<<8192, 256>>>(wg, wgs, (long)E_EXP * HP, I_DIM);
    split_w_kernel<<<8192, 256>>>(wu, wus, (long)E_EXP * HP, I_DIM);
    split_w_kernel<<<8192, 256>>>(wd, wds, (long)E_EXP * IP, H_DIM);

    dim3 g1(T_TOK / 128, I_DIM / 64, E_EXP);
    ffn1_kernel<<<g1, 256, 4 * F1_STG * 8>>>();
    dim3 g2(T_TOK / 128, H_DIM / 128, E_EXP);
    ffn2_kernel<<<g2, 256, 4 * F2_STG * 8>>>();

    combine_kernel<<<(T_TOK * H_DIM + 255) / 256, 256>>>(out);
}